// round 2
// baseline (speedup 1.0000x reference)
#include <cuda_runtime.h>

// PersistenceLandscapeEncoder: pairs (32768,2) f32 -> landscapes (5,4096) f32.
// tent_i(t) = min(t - b_i, d_i - t) floored at 0  ==  max(0, h_i - |t - m_i|)
// with m = (b+d)/2, h = (d-b)/2.  out[k][j] = (k+1)-th largest tent at t_j.
//
// Strategy: bucket pairs by midpoint m into NB buckets. For each column t,
// expand outward from the bucket containing t; a bucket at min-distance D from
// t can only contribute values <= h_max - D, so once h_max - D <= current top4
// the rest of that side is pruned (conservative & exact).

#define N_PAIRS 32768
#define RES     4096
#define NB      512
#define SPLIT   8          // threads cooperating per column
#define PAD     1e-5f      // bucket-boundary rounding slack (weakens prune only)

__device__ float  g_tmin, g_tmax, g_hmax;
__device__ int    g_start[NB + 1];
__device__ float2 g_mh[N_PAIRS];      // bucketed (m, h)

// ---------------------------------------------------------------------------
// Prep: minmax -> histogram -> scan -> scatter (single block).
// ---------------------------------------------------------------------------
__global__ void prep_kernel(const float2* __restrict__ pairs) {
    __shared__ float red[1024];
    __shared__ float red2[1024];
    __shared__ int   hist[NB];
    __shared__ int   sc[NB];
    __shared__ float s_tmin, s_scale;

    const int tid = threadIdx.x;

    // min(birth) / max(death)
    float mn = 3.0e38f, mx = -3.0e38f;
    for (int i = tid; i < N_PAIRS; i += 1024) {
        float2 p = pairs[i];
        mn = fminf(mn, p.x);
        mx = fmaxf(mx, p.y);
    }
    red[tid] = mn; red2[tid] = mx;
    __syncthreads();
    for (int s = 512; s > 0; s >>= 1) {
        if (tid < s) {
            red[tid]  = fminf(red[tid],  red[tid + s]);
            red2[tid] = fmaxf(red2[tid], red2[tid + s]);
        }
        __syncthreads();
    }
    if (tid == 0) {
        g_tmin = red[0]; g_tmax = red2[0];
        s_tmin = red[0];
        s_scale = (float)NB / fmaxf(red2[0] - red[0], 1e-30f);
    }
    if (tid < NB) hist[tid] = 0;
    __syncthreads();

    const float tmin = s_tmin, scale = s_scale;

    // histogram over midpoint buckets + global h_max
    float hm = 0.0f;
    for (int i = tid; i < N_PAIRS; i += 1024) {
        float2 p = pairs[i];
        float m = 0.5f * (p.x + p.y);
        float h = 0.5f * (p.y - p.x);
        hm = fmaxf(hm, h);
        int b = (int)((m - tmin) * scale);
        b = min(NB - 1, max(0, b));
        atomicAdd(&hist[b], 1);
    }
    red[tid] = hm;
    __syncthreads();
    for (int s = 512; s > 0; s >>= 1) {
        if (tid < s) red[tid] = fmaxf(red[tid], red[tid + s]);
        __syncthreads();
    }
    if (tid == 0) g_hmax = red[0];

    // inclusive Hillis-Steele scan of hist -> sc
    if (tid < NB) sc[tid] = hist[tid];
    __syncthreads();
    for (int off = 1; off < NB; off <<= 1) {
        int v = 0;
        if (tid < NB && tid >= off) v = sc[tid - off];
        __syncthreads();
        if (tid < NB) sc[tid] += v;
        __syncthreads();
    }

    // exclusive starts; reuse hist[] as scatter cursors
    if (tid < NB) {
        int ex = sc[tid] - hist[tid];
        g_start[tid] = ex;
        hist[tid] = ex;
    }
    if (tid == 0) g_start[NB] = N_PAIRS;
    __syncthreads();

    // scatter (m, h) into bucket order
    for (int i = tid; i < N_PAIRS; i += 1024) {
        float2 p = pairs[i];
        float m = 0.5f * (p.x + p.y);
        float h = 0.5f * (p.y - p.x);
        int b = (int)((m - tmin) * scale);
        b = min(NB - 1, max(0, b));
        int pos = atomicAdd(&hist[b], 1);
        g_mh[pos] = make_float2(m, h);
    }
}

// ---------------------------------------------------------------------------
// Main: SPLIT threads per column, ring expansion with prune, shfl merge.
// ---------------------------------------------------------------------------
__device__ __forceinline__ void scan_bucket(
    int b, int sub, float t,
    float& t0, float& t1, float& t2, float& t3, float& t4)
{
    const int e = g_start[b + 1];
    for (int i = g_start[b] + sub; i < e; i += SPLIT) {
        float2 mh = g_mh[i];
        float v = mh.y - fabsf(t - mh.x);
        if (v > t4) {
            t4 = v;
            if (t4 > t3) { float tmp = t4; t4 = t3; t3 = tmp;
              if (t3 > t2) { tmp = t3; t3 = t2; t2 = tmp;
                if (t2 > t1) { tmp = t2; t2 = t1; t1 = tmp;
                  if (t1 > t0) { tmp = t1; t1 = t0; t0 = tmp; }
                }
              }
            }
        }
    }
}

__global__ void __launch_bounds__(128) landscape_kernel(float* __restrict__ out)
{
    const int gt  = blockIdx.x * 128 + threadIdx.x;   // 0 .. RES*SPLIT-1
    const int col = gt / SPLIT;
    const int sub = gt % SPLIT;

    const float tmin = g_tmin, tmax = g_tmax, hmax = g_hmax;
    const float span = tmax - tmin;
    const float W = span / (float)NB;
    const float t = tmin + (float)col * (span / (float)(RES - 1));

    float t0 = 0.0f, t1 = 0.0f, t2 = 0.0f, t3 = 0.0f, t4 = 0.0f;

    int cb = (int)((t - tmin) * ((float)NB / fmaxf(span, 1e-30f)));
    cb = min(NB - 1, max(0, cb));

    scan_bucket(cb, sub, t, t0, t1, t2, t3, t4);

    bool ld = false, rd = false;
    for (int r = 1; !(ld && rd); r++) {
        if (!ld) {
            int b = cb - r;
            if (b < 0) ld = true;
            else {
                float upper = tmin + (float)(b + 1) * W + PAD;
                float dist  = fmaxf(0.0f, t - upper);
                if (hmax - dist <= t4) ld = true;   // all further-left pruned
                else scan_bucket(b, sub, t, t0, t1, t2, t3, t4);
            }
        }
        if (!rd) {
            int b = cb + r;
            if (b >= NB) rd = true;
            else {
                float lower = tmin + (float)b * W - PAD;
                float dist  = fmaxf(0.0f, lower - t);
                if (hmax - dist <= t4) rd = true;   // all further-right pruned
                else scan_bucket(b, sub, t, t0, t1, t2, t3, t4);
            }
        }
    }

    // Merge sorted-descending 5-lists across the SPLIT-subgroup (butterfly).
    // m[k] = max(a[k], b[k], max_{i+j=k-1} min(a[i], b[j]))
    #pragma unroll
    for (int off = 1; off < SPLIT; off <<= 1) {
        float b0 = __shfl_xor_sync(0xffffffffu, t0, off);
        float b1 = __shfl_xor_sync(0xffffffffu, t1, off);
        float b2 = __shfl_xor_sync(0xffffffffu, t2, off);
        float b3 = __shfl_xor_sync(0xffffffffu, t3, off);
        float b4 = __shfl_xor_sync(0xffffffffu, t4, off);

        float m0 = fmaxf(t0, b0);
        float m1 = fmaxf(fmaxf(t1, b1), fminf(t0, b0));
        float m2 = fmaxf(fmaxf(t2, b2), fmaxf(fminf(t0, b1), fminf(t1, b0)));
        float m3 = fmaxf(fmaxf(t3, b3),
                   fmaxf(fminf(t0, b2), fmaxf(fminf(t1, b1), fminf(t2, b0))));
        float m4 = fmaxf(fmaxf(t4, b4),
                   fmaxf(fmaxf(fminf(t0, b3), fminf(t1, b2)),
                         fmaxf(fminf(t2, b1), fminf(t3, b0))));
        t0 = m0; t1 = m1; t2 = m2; t3 = m3; t4 = m4;
    }

    if (sub == 0) {
        out[0 * RES + col] = t0;
        out[1 * RES + col] = t1;
        out[2 * RES + col] = t2;
        out[3 * RES + col] = t3;
        out[4 * RES + col] = t4;
    }
}

extern "C" void kernel_launch(void* const* d_in, const int* in_sizes, int n_in,
                              void* d_out, int out_size) {
    const float2* pairs = (const float2*)d_in[0];
    float* out = (float*)d_out;

    prep_kernel<<<1, 1024>>>(pairs);
    landscape_kernel<<<(RES * SPLIT) / 128, 128>>>(out);
}

// round 3
// speedup vs baseline: 4.7269x; 4.7269x over previous
#include <cuda_runtime.h>

// PersistenceLandscapeEncoder: pairs (32768,2) f32 -> landscapes (5,4096) f32.
// tent_i(t) = min(t-b_i, d_i-t) clamped at 0.  For m_i=(b+d)/2 < t the value is
// exactly d_i - t; for m_i > t it is t - b_i.  So per column:
//   top5(t) = top5 of { prefixTop5d(<t) - t } U { t - suffixBot5b(>t) } U homeBucket
// Buckets over m give exact classification; only the home bucket is evaluated
// directly. Prefix/suffix 5-lists precomputed once.

#define N_PAIRS 32768
#define RES     4096
#define NB      512
#define CAP     320
#define SPLIT   8
#define NEGINF  (-3.0e38f)
#define POSINF  (3.0e38f)

__device__ float  g_tmin, g_tmax, g_scale;
__device__ int    g_count[NB];
__device__ float2 g_slab[NB * CAP];     // (birth, death) per bucket slot
__device__ float  g_bT[NB][5];          // per-bucket top-5 death (desc)
__device__ float  g_bB[NB][5];          // per-bucket bot-5 birth (asc)
__device__ float  g_P[NB][5];           // exclusive prefix top-5 death (desc)
__device__ float  g_S[NB][5];           // exclusive suffix bot-5 birth (asc)

// ---- sorted 5-list merge networks (all static indices) ---------------------
__device__ __forceinline__ void merge_desc(
    float& a0, float& a1, float& a2, float& a3, float& a4,
    float b0, float b1, float b2, float b3, float b4)
{
    float m0 = fmaxf(a0, b0);
    float m1 = fmaxf(fmaxf(a1, b1), fminf(a0, b0));
    float m2 = fmaxf(fmaxf(a2, b2), fmaxf(fminf(a0, b1), fminf(a1, b0)));
    float m3 = fmaxf(fmaxf(a3, b3),
               fmaxf(fminf(a0, b2), fmaxf(fminf(a1, b1), fminf(a2, b0))));
    float m4 = fmaxf(fmaxf(a4, b4),
               fmaxf(fmaxf(fminf(a0, b3), fminf(a1, b2)),
                     fmaxf(fminf(a2, b1), fminf(a3, b0))));
    a0 = m0; a1 = m1; a2 = m2; a3 = m3; a4 = m4;
}

__device__ __forceinline__ void merge_asc(
    float& a0, float& a1, float& a2, float& a3, float& a4,
    float b0, float b1, float b2, float b3, float b4)
{
    float m0 = fminf(a0, b0);
    float m1 = fminf(fminf(a1, b1), fmaxf(a0, b0));
    float m2 = fminf(fminf(a2, b2), fminf(fmaxf(a0, b1), fmaxf(a1, b0)));
    float m3 = fminf(fminf(a3, b3),
               fminf(fmaxf(a0, b2), fminf(fmaxf(a1, b1), fmaxf(a2, b0))));
    float m4 = fminf(fminf(a4, b4),
               fminf(fminf(fmaxf(a0, b3), fmaxf(a1, b2)),
                     fminf(fmaxf(a2, b1), fmaxf(a3, b0))));
    a0 = m0; a1 = m1; a2 = m2; a3 = m3; a4 = m4;
}

__device__ __forceinline__ void insert_desc(
    float& t0, float& t1, float& t2, float& t3, float& t4, float v)
{
    if (v > t4) {
        t4 = v;
        if (t4 > t3) { float x = t4; t4 = t3; t3 = x;
          if (t3 > t2) { x = t3; t3 = t2; t2 = x;
            if (t2 > t1) { x = t2; t2 = t1; t1 = x;
              if (t1 > t0) { x = t1; t1 = t0; t0 = x; }
            }
          }
        }
    }
}

__device__ __forceinline__ void insert_asc(
    float& t0, float& t1, float& t2, float& t3, float& t4, float v)
{
    if (v < t4) {
        t4 = v;
        if (t4 < t3) { float x = t4; t4 = t3; t3 = x;
          if (t3 < t2) { x = t3; t3 = t2; t2 = x;
            if (t2 < t1) { x = t2; t2 = t1; t1 = x;
              if (t1 < t0) { x = t1; t1 = t0; t0 = x; }
            }
          }
        }
    }
}

// ---------------------------------------------------------------------------
// K1: single-block minmax + reset counters (graph-replay safe reinit).
// ---------------------------------------------------------------------------
__global__ void minmax_kernel(const float2* __restrict__ pairs) {
    __shared__ float smn[1024];
    __shared__ float smx[1024];
    const int tid = threadIdx.x;
    if (tid < NB) g_count[tid] = 0;
    float mn = POSINF, mx = NEGINF;
    for (int i = tid; i < N_PAIRS; i += 1024) {
        float2 p = pairs[i];
        mn = fminf(mn, p.x);
        mx = fmaxf(mx, p.y);
    }
    smn[tid] = mn; smx[tid] = mx;
    __syncthreads();
    for (int s = 512; s > 0; s >>= 1) {
        if (tid < s) {
            smn[tid] = fminf(smn[tid], smn[tid + s]);
            smx[tid] = fmaxf(smx[tid], smx[tid + s]);
        }
        __syncthreads();
    }
    if (tid == 0) {
        g_tmin = smn[0];
        g_tmax = smx[0];
        g_scale = (float)NB / fmaxf(smx[0] - smn[0], 1e-30f);
    }
}

// ---------------------------------------------------------------------------
// K2: scatter pairs into fixed-capacity midpoint buckets.
// ---------------------------------------------------------------------------
__global__ void __launch_bounds__(256) scatter_kernel(const float2* __restrict__ pairs) {
    const float tmin = g_tmin, scale = g_scale;
    const int i = blockIdx.x * 256 + threadIdx.x;
    if (i < N_PAIRS) {
        float2 p = pairs[i];
        float m = 0.5f * (p.x + p.y);
        int b = (int)((m - tmin) * scale);
        b = min(NB - 1, max(0, b));
        int pos = atomicAdd(&g_count[b], 1);
        if (pos < CAP) g_slab[b * CAP + pos] = p;
    }
}

// ---------------------------------------------------------------------------
// K3: warp per bucket -> top-5 death (desc), bot-5 birth (asc).
// ---------------------------------------------------------------------------
__global__ void __launch_bounds__(512) buckettop_kernel() {
    const int warp = (blockIdx.x * 512 + threadIdx.x) >> 5;
    const int lane = threadIdx.x & 31;
    if (warp >= NB) return;
    const int n = min(g_count[warp], CAP);

    float d0 = NEGINF, d1 = NEGINF, d2 = NEGINF, d3 = NEGINF, d4 = NEGINF;
    float b0 = POSINF, b1 = POSINF, b2 = POSINF, b3 = POSINF, b4 = POSINF;
    const float2* s = &g_slab[warp * CAP];
    for (int i = lane; i < n; i += 32) {
        float2 p = s[i];
        insert_desc(d0, d1, d2, d3, d4, p.y);
        insert_asc (b0, b1, b2, b3, b4, p.x);
    }
    #pragma unroll
    for (int off = 16; off >= 1; off >>= 1) {
        float e0 = __shfl_xor_sync(0xffffffffu, d0, off);
        float e1 = __shfl_xor_sync(0xffffffffu, d1, off);
        float e2 = __shfl_xor_sync(0xffffffffu, d2, off);
        float e3 = __shfl_xor_sync(0xffffffffu, d3, off);
        float e4 = __shfl_xor_sync(0xffffffffu, d4, off);
        merge_desc(d0, d1, d2, d3, d4, e0, e1, e2, e3, e4);
        e0 = __shfl_xor_sync(0xffffffffu, b0, off);
        e1 = __shfl_xor_sync(0xffffffffu, b1, off);
        e2 = __shfl_xor_sync(0xffffffffu, b2, off);
        e3 = __shfl_xor_sync(0xffffffffu, b3, off);
        e4 = __shfl_xor_sync(0xffffffffu, b4, off);
        merge_asc(b0, b1, b2, b3, b4, e0, e1, e2, e3, e4);
    }
    if (lane == 0) {
        g_bT[warp][0] = d0; g_bT[warp][1] = d1; g_bT[warp][2] = d2;
        g_bT[warp][3] = d3; g_bT[warp][4] = d4;
        g_bB[warp][0] = b0; g_bB[warp][1] = b1; g_bB[warp][2] = b2;
        g_bB[warp][3] = b3; g_bB[warp][4] = b4;
    }
}

// ---------------------------------------------------------------------------
// K4: one block -> exclusive prefix (top-5 d) & exclusive suffix (bot-5 b).
// ---------------------------------------------------------------------------
__global__ void __launch_bounds__(512) scan_kernel() {
    __shared__ float s0[NB], s1[NB], s2[NB], s3[NB], s4[NB];
    const int tid = threadIdx.x;

    // exclusive prefix of bucket top-5 d (desc)
    float a0 = NEGINF, a1 = NEGINF, a2 = NEGINF, a3 = NEGINF, a4 = NEGINF;
    if (tid > 0) {
        a0 = g_bT[tid-1][0]; a1 = g_bT[tid-1][1]; a2 = g_bT[tid-1][2];
        a3 = g_bT[tid-1][3]; a4 = g_bT[tid-1][4];
    }
    s0[tid]=a0; s1[tid]=a1; s2[tid]=a2; s3[tid]=a3; s4[tid]=a4;
    __syncthreads();
    for (int off = 1; off < NB; off <<= 1) {
        float e0=NEGINF,e1=NEGINF,e2=NEGINF,e3=NEGINF,e4=NEGINF;
        if (tid >= off) { e0=s0[tid-off]; e1=s1[tid-off]; e2=s2[tid-off];
                          e3=s3[tid-off]; e4=s4[tid-off]; }
        __syncthreads();
        merge_desc(a0, a1, a2, a3, a4, e0, e1, e2, e3, e4);
        s0[tid]=a0; s1[tid]=a1; s2[tid]=a2; s3[tid]=a3; s4[tid]=a4;
        __syncthreads();
    }
    g_P[tid][0]=a0; g_P[tid][1]=a1; g_P[tid][2]=a2; g_P[tid][3]=a3; g_P[tid][4]=a4;
    __syncthreads();

    // exclusive suffix of bucket bot-5 b (asc)
    a0 = POSINF; a1 = POSINF; a2 = POSINF; a3 = POSINF; a4 = POSINF;
    if (tid < NB - 1) {
        a0 = g_bB[tid+1][0]; a1 = g_bB[tid+1][1]; a2 = g_bB[tid+1][2];
        a3 = g_bB[tid+1][3]; a4 = g_bB[tid+1][4];
    }
    s0[tid]=a0; s1[tid]=a1; s2[tid]=a2; s3[tid]=a3; s4[tid]=a4;
    __syncthreads();
    for (int off = 1; off < NB; off <<= 1) {
        float e0=POSINF,e1=POSINF,e2=POSINF,e3=POSINF,e4=POSINF;
        if (tid + off < NB) { e0=s0[tid+off]; e1=s1[tid+off]; e2=s2[tid+off];
                              e3=s3[tid+off]; e4=s4[tid+off]; }
        __syncthreads();
        merge_asc(a0, a1, a2, a3, a4, e0, e1, e2, e3, e4);
        s0[tid]=a0; s1[tid]=a1; s2[tid]=a2; s3[tid]=a3; s4[tid]=a4;
        __syncthreads();
    }
    g_S[tid][0]=a0; g_S[tid][1]=a1; g_S[tid][2]=a2; g_S[tid][3]=a3; g_S[tid][4]=a4;
}

// ---------------------------------------------------------------------------
// K5: SPLIT threads per column: home-bucket scan + prefix/suffix merge.
// ---------------------------------------------------------------------------
__global__ void __launch_bounds__(256) landscape_kernel(float* __restrict__ out)
{
    const int gt  = blockIdx.x * 256 + threadIdx.x;
    const int col = gt / SPLIT;
    const int sub = gt % SPLIT;

    const float tmin = g_tmin, tmax = g_tmax, scale = g_scale;
    const float t = tmin + (float)col * ((tmax - tmin) / (float)(RES - 1));

    int cb = (int)((t - tmin) * scale);
    cb = min(NB - 1, max(0, cb));

    float t0 = 0.0f, t1 = 0.0f, t2 = 0.0f, t3 = 0.0f, t4 = 0.0f;

    // home bucket: exact tent evaluation
    const int n = min(g_count[cb], CAP);
    const float2* s = &g_slab[cb * CAP];
    for (int i = sub; i < n; i += SPLIT) {
        float2 p = s[i];
        float v = fminf(t - p.x, p.y - t);
        insert_desc(t0, t1, t2, t3, t4, v);
    }

    // sub 0 folds in the prefix list (values d - t, clamped, still desc);
    // sub 1 folds in the suffix list (values t - b, clamped, still desc).
    if (sub == 0) {
        merge_desc(t0, t1, t2, t3, t4,
                   fmaxf(g_P[cb][0] - t, 0.0f), fmaxf(g_P[cb][1] - t, 0.0f),
                   fmaxf(g_P[cb][2] - t, 0.0f), fmaxf(g_P[cb][3] - t, 0.0f),
                   fmaxf(g_P[cb][4] - t, 0.0f));
    } else if (sub == 1) {
        merge_desc(t0, t1, t2, t3, t4,
                   fmaxf(t - g_S[cb][0], 0.0f), fmaxf(t - g_S[cb][1], 0.0f),
                   fmaxf(t - g_S[cb][2], 0.0f), fmaxf(t - g_S[cb][3], 0.0f),
                   fmaxf(t - g_S[cb][4], 0.0f));
    }

    // butterfly merge across the 8-lane column group
    #pragma unroll
    for (int off = 1; off < SPLIT; off <<= 1) {
        float e0 = __shfl_xor_sync(0xffffffffu, t0, off);
        float e1 = __shfl_xor_sync(0xffffffffu, t1, off);
        float e2 = __shfl_xor_sync(0xffffffffu, t2, off);
        float e3 = __shfl_xor_sync(0xffffffffu, t3, off);
        float e4 = __shfl_xor_sync(0xffffffffu, t4, off);
        merge_desc(t0, t1, t2, t3, t4, e0, e1, e2, e3, e4);
    }

    if (sub == 0) {
        out[0 * RES + col] = t0;
        out[1 * RES + col] = t1;
        out[2 * RES + col] = t2;
        out[3 * RES + col] = t3;
        out[4 * RES + col] = t4;
    }
}

extern "C" void kernel_launch(void* const* d_in, const int* in_sizes, int n_in,
                              void* d_out, int out_size) {
    const float2* pairs = (const float2*)d_in[0];
    float* out = (float*)d_out;

    minmax_kernel<<<1, 1024>>>(pairs);
    scatter_kernel<<<(N_PAIRS + 255) / 256, 256>>>(pairs);
    buckettop_kernel<<<NB / 16, 512>>>();
    scan_kernel<<<1, NB>>>();
    landscape_kernel<<<RES * SPLIT / 256, 256>>>(out);
}